// round 13
// baseline (speedup 1.0000x reference)
#include <cuda_runtime.h>
#include <cuda_fp16.h>
#include <cstdint>
#include <math.h>

#define B_ 8192
#define D_ 512
#define C_ 1000
#define CP_ 1024
#define K_ 8
#define EPSV 1e-8f
#define TEMPV 0.2f
#define NEGV -10000.0f

// ---------------------------------------------------------------------------
// Scratch (__device__ globals)
// ---------------------------------------------------------------------------
__device__ __half g_z0[(size_t)B_ * D_];
__device__ __half g_z1[(size_t)B_ * D_];
__device__ __half g_w1t0[(size_t)K_ * D_ * D_];
__device__ __half g_w1t1[(size_t)K_ * D_ * D_];
__device__ __half g_w2t0[(size_t)K_ * CP_ * D_];
__device__ __half g_w2t1[(size_t)K_ * CP_ * D_];
__device__ __half g_h0[(size_t)K_ * B_ * D_];
__device__ __half g_h1[(size_t)K_ * B_ * D_];
__device__ float g_logits[(size_t)B_ * K_ * CP_];

// ---------------------------------------------------------------------------
// PTX helpers
// ---------------------------------------------------------------------------
__device__ __forceinline__ uint32_t smem_u32(const void* p) {
    uint32_t a;
    asm("{ .reg .u64 t; cvta.to.shared.u64 t, %1; cvt.u32.u64 %0, t; }" : "=r"(a) : "l"(p));
    return a;
}
__device__ __forceinline__ void cp_async16(uint32_t s, const void* g) {
    asm volatile("cp.async.cg.shared.global [%0], [%1], 16;" :: "r"(s), "l"(g));
}
__device__ __forceinline__ void cp_commit() { asm volatile("cp.async.commit_group;"); }
template <int N>
__device__ __forceinline__ void cp_wait() { asm volatile("cp.async.wait_group %0;" :: "n"(N)); }

__device__ __forceinline__ void ldsm4(uint32_t* r, uint32_t addr) {
    asm volatile("ldmatrix.sync.aligned.m8n8.x4.shared.b16 {%0,%1,%2,%3}, [%4];"
                 : "=r"(r[0]), "=r"(r[1]), "=r"(r[2]), "=r"(r[3]) : "r"(addr));
}
__device__ __forceinline__ void mma16816(float* c, const uint32_t* a, uint32_t b0, uint32_t b1) {
    asm volatile(
        "mma.sync.aligned.m16n8k16.row.col.f32.f16.f16.f32 "
        "{%0,%1,%2,%3}, {%4,%5,%6,%7}, {%8,%9}, {%0,%1,%2,%3};"
        : "+f"(c[0]), "+f"(c[1]), "+f"(c[2]), "+f"(c[3])
        : "r"(a[0]), "r"(a[1]), "r"(a[2]), "r"(a[3]), "r"(b0), "r"(b1));
}

// 2-limb fp16 split: x = a + b + O(2^-22 |x|)
__device__ __forceinline__ void split2(float x, __half& a, __half& b) {
    a = __float2half_rn(x);
    b = __float2half_rn(x - __half2float(a));
}

// ---------------------------------------------------------------------------
// Merged conversion kernel (one launch: z split + W1/W2 transpose-split)
// ---------------------------------------------------------------------------
#define NB_Z  (B_ * D_ / 4 / 256)            // 4096
#define NB_W1 ((D_ / 32) * (D_ / 32) * K_)   // 2048
#define NB_W2 ((CP_ / 32) * (D_ / 32) * K_)  // 4096

__device__ __forceinline__ void trsplit_body(
    const float* __restrict__ in, __half* __restrict__ o0, __half* __restrict__ o1,
    int Nin, int Npad, int bx, int by, int k, int tid)
{
    __shared__ float t[32][33];
    const int n0 = bx * 32, d0 = by * 32;
    const int tx = tid & 31, ty = tid >> 5;
    const float* src = in + (size_t)k * D_ * Nin;
#pragma unroll
    for (int r = 0; r < 4; r++) {
        int d = d0 + ty + r * 8, n = n0 + tx;
        t[ty + r * 8][tx] = (n < Nin) ? src[(size_t)d * Nin + n] : 0.0f;
    }
    __syncthreads();
    size_t obase = (size_t)k * Npad * D_;
#pragma unroll
    for (int r = 0; r < 4; r++) {
        int nl = ty + r * 8;
        float v = t[tx][nl];
        __half a, b;
        split2(v, a, b);
        size_t oi = obase + (size_t)(n0 + nl) * D_ + d0 + tx;
        o0[oi] = a; o1[oi] = b;
    }
}

__global__ void __launch_bounds__(256) convert_all_kernel(
    const float* __restrict__ z, const float* __restrict__ W1,
    const float* __restrict__ W2,
    __half* __restrict__ z0, __half* __restrict__ z1,
    __half* __restrict__ w10, __half* __restrict__ w11,
    __half* __restrict__ w20, __half* __restrict__ w21)
{
    const int blk = blockIdx.x;
    const int tid = threadIdx.x;
    if (blk < NB_Z) {
        int i = blk * 256 + tid;
        float4 v = ((const float4*)z)[i];
        __half a0, b0, a1, b1, a2, b2, a3, b3;
        split2(v.x, a0, b0); split2(v.y, a1, b1);
        split2(v.z, a2, b2); split2(v.w, a3, b3);
        ((__half2*)z0)[i * 2]     = __half2(a0, a1);
        ((__half2*)z0)[i * 2 + 1] = __half2(a2, a3);
        ((__half2*)z1)[i * 2]     = __half2(b0, b1);
        ((__half2*)z1)[i * 2 + 1] = __half2(b2, b3);
    } else if (blk < NB_Z + NB_W1) {
        int r = blk - NB_Z;
        int bx = r & 15; r >>= 4;
        int by = r & 15; r >>= 4;
        trsplit_body(W1, w10, w11, D_, D_, bx, by, r, tid);
    } else {
        int r = blk - NB_Z - NB_W1;
        int bx = r & 31; r >>= 5;
        int by = r & 15; r >>= 4;
        trsplit_body(W2, w20, w21, C_, CP_, bx, by, r, tid);
    }
}

// ---------------------------------------------------------------------------
// HMMA fp16 GEMM with 3-product 2-limb split. (unchanged — proven)
// ---------------------------------------------------------------------------
#define TILE_B 8192
#define STAGE_B (4 * TILE_B)
#define NSTAGE 3
#define NCHUNK 16
#define EPI_PITCH_H 272
#define EPI_PITCH_F 528

template <bool SPLIT>
__global__ void __launch_bounds__(256, 2) tc_gemm(
    const __half* __restrict__ A0, const __half* __restrict__ A1, long long aStr,
    const __half* __restrict__ B0, const __half* __restrict__ B1, long long bStr,
    const float* __restrict__ bias, int biasStr, int Nreal,
    float* __restrict__ outF, int outLd,
    __half* __restrict__ O0, __half* __restrict__ O1)
{
    extern __shared__ __align__(16) char dsm[];
    const uint32_t sbase = smem_u32(dsm);

    const int tid = threadIdx.x;
    const int warp = tid >> 5, lane = tid & 31;
    const int bz = blockIdx.z;
    const int m0 = blockIdx.y * 128, n0 = blockIdx.x * 128;
    const int warpM = (warp >> 2) * 64;
    const int warpN = (warp & 3) * 32;

    const char* gp[4];
    gp[0] = (const char*)A0 + ((size_t)bz * aStr + (size_t)m0 * D_) * 2;
    gp[1] = (const char*)A1 + ((size_t)bz * aStr + (size_t)m0 * D_) * 2;
    gp[2] = (const char*)B0 + ((size_t)bz * bStr + (size_t)n0 * D_) * 2;
    gp[3] = (const char*)B1 + ((size_t)bz * bStr + (size_t)n0 * D_) * 2;

    const int ldRow0 = tid >> 2, ldC0 = tid & 3;
    const int ldRow1 = (tid + 256) >> 2, ldC1 = (tid + 256) & 3;
    const uint32_t ldDst0 = (uint32_t)ldRow0 * 64 + (uint32_t)((ldC0 ^ ((ldRow0 >> 1) & 3)) << 4);
    const uint32_t ldDst1 = (uint32_t)ldRow1 * 64 + (uint32_t)((ldC1 ^ ((ldRow1 >> 1) & 3)) << 4);
    const size_t ldSrc0 = (size_t)ldRow0 * 1024 + ldC0 * 16;
    const size_t ldSrc1 = (size_t)ldRow1 * 1024 + ldC1 * 16;

    auto load_stage = [&](int kk, int buf) {
        const size_t koff = (size_t)kk * 64;
#pragma unroll
        for (int t = 0; t < 4; t++) {
            uint32_t sb = sbase + buf * STAGE_B + t * TILE_B;
            const char* g = gp[t] + koff;
            cp_async16(sb + ldDst0, g + ldSrc0);
            cp_async16(sb + ldDst1, g + ldSrc1);
        }
        cp_commit();
    };

    float acc[4][4][4];
#pragma unroll
    for (int i = 0; i < 4; i++)
#pragma unroll
        for (int j = 0; j < 4; j++)
#pragma unroll
            for (int r = 0; r < 4; r++) acc[i][j][r] = 0.0f;

    load_stage(0, 0);
    load_stage(1, 1);

    const int rowA = warpM + (lane & 15);
    const uint32_t swA = (uint32_t)((rowA >> 1) & 3);
    const uint32_t cA = (uint32_t)(lane >> 4);
    const uint32_t aBase = (uint32_t)rowA * 64;

    const int rowB = warpN + (lane & 7) + ((lane >> 4) & 1) * 8;
    const uint32_t swB = (uint32_t)((rowB >> 1) & 3);
    const uint32_t cB = (uint32_t)((lane >> 3) & 1);
    const uint32_t bBase = (uint32_t)rowB * 64;

    for (int kk = 0; kk < NCHUNK; kk++) {
        if (kk == NCHUNK - 1) cp_wait<0>(); else cp_wait<1>();
        __syncthreads();
        if (kk + 2 < NCHUNK) load_stage(kk + 2, (kk + 2) % NSTAGE);

        const uint32_t sb = sbase + (kk % NSTAGE) * STAGE_B;

#pragma unroll
        for (int ks = 0; ks < 2; ks++) {
            const uint32_t aOff = aBase + (((ks * 2 + cA) ^ swA) << 4);
            const uint32_t bOff = bBase + (((ks * 2 + cB) ^ swB) << 4);
            uint32_t a0f[4][4], b0f[2][4];
#pragma unroll
            for (int i = 0; i < 4; i++)
                ldsm4(a0f[i], sb + 0 * TILE_B + aOff + i * 1024);
#pragma unroll
            for (int jp = 0; jp < 2; jp++)
                ldsm4(b0f[jp], sb + 2 * TILE_B + bOff + jp * 1024);
#pragma unroll
            for (int i = 0; i < 4; i++)
#pragma unroll
                for (int j = 0; j < 4; j++)
                    mma16816(acc[i][j], a0f[i], b0f[j >> 1][(j & 1) * 2],
                             b0f[j >> 1][(j & 1) * 2 + 1]);
            {
                uint32_t b1f[2][4];
#pragma unroll
                for (int jp = 0; jp < 2; jp++)
                    ldsm4(b1f[jp], sb + 3 * TILE_B + bOff + jp * 1024);
#pragma unroll
                for (int i = 0; i < 4; i++)
#pragma unroll
                    for (int j = 0; j < 4; j++)
                        mma16816(acc[i][j], a0f[i], b1f[j >> 1][(j & 1) * 2],
                                 b1f[j >> 1][(j & 1) * 2 + 1]);
            }
            {
                uint32_t a1f[4][4];
#pragma unroll
                for (int i = 0; i < 4; i++)
                    ldsm4(a1f[i], sb + 1 * TILE_B + aOff + i * 1024);
#pragma unroll
                for (int i = 0; i < 4; i++)
#pragma unroll
                    for (int j = 0; j < 4; j++)
                        mma16816(acc[i][j], a1f[i], b0f[j >> 1][(j & 1) * 2],
                                 b0f[j >> 1][(j & 1) * 2 + 1]);
            }
        }
    }

    // ---------------- epilogue: smem-staged, coalesced global writes --------
    __syncthreads();

    const int rBase = warpM + (lane >> 2);
    const int cBaseH = warpN + (lane & 3) * 2;

    float bj[4][2];
#pragma unroll
    for (int j = 0; j < 4; j++)
#pragma unroll
        for (int t = 0; t < 2; t++) {
            int n = n0 + cBaseH + j * 8 + t;
            bj[j][t] = (SPLIT || n < Nreal) ? bias[bz * biasStr + n] : 0.0f;
        }

    if (SPLIT) {
#pragma unroll
        for (int i = 0; i < 4; i++)
#pragma unroll
            for (int j = 0; j < 4; j++)
#pragma unroll
                for (int half = 0; half < 2; half++) {
                    const int r = rBase + i * 16 + half * 8;
                    const int c = cBaseH + j * 8;
                    float v0 = fmaxf(acc[i][j][half * 2]     + bj[j][0], 0.0f);
                    float v1 = fmaxf(acc[i][j][half * 2 + 1] + bj[j][1], 0.0f);
                    __half a0, b0, a1, b1;
                    split2(v0, a0, b0);
                    split2(v1, a1, b1);
                    *(__half2*)(dsm + r * EPI_PITCH_H + c * 2) = __half2(a0, a1);
                    *(__half2*)(dsm + 128 * EPI_PITCH_H + r * EPI_PITCH_H + c * 2) = __half2(b0, b1);
                }
        __syncthreads();
#pragma unroll
        for (int it = 0; it < 8; it++) {
            int idx = tid + it * 256;
            int r = idx >> 4, c16 = idx & 15;
            float4 w0 = *(const float4*)(dsm + r * EPI_PITCH_H + c16 * 16);
            float4 w1 = *(const float4*)(dsm + 128 * EPI_PITCH_H + r * EPI_PITCH_H + c16 * 16);
            size_t gb = ((size_t)bz * B_ + m0 + r) * D_ + n0 + c16 * 8;
            *(float4*)&O0[gb] = w0;
            *(float4*)&O1[gb] = w1;
        }
    } else {
#pragma unroll
        for (int i = 0; i < 4; i++)
#pragma unroll
            for (int j = 0; j < 4; j++)
#pragma unroll
                for (int half = 0; half < 2; half++) {
                    const int r = rBase + i * 16 + half * 8;
                    const int c = cBaseH + j * 8;
                    float2 vv = make_float2(acc[i][j][half * 2]     + bj[j][0],
                                            acc[i][j][half * 2 + 1] + bj[j][1]);
                    *(float2*)(dsm + r * EPI_PITCH_F + c * 4) = vv;
                }
        __syncthreads();
#pragma unroll
        for (int it = 0; it < 16; it++) {
            int idx = tid + it * 256;
            int r = idx >> 5, c4 = idx & 31;
            float4 w = *(const float4*)(dsm + r * EPI_PITCH_F + c4 * 16);
            *(float4*)&outF[((size_t)(m0 + r) * K_ + bz) * outLd + n0 + c4 * 4] = w;
        }
    }
}

// ---------------------------------------------------------------------------
// Gating kernel v4 — register-resident, 4 samples per block,
// Gram reduction 3 butterfly steps + 32-partial finalize.
// ---------------------------------------------------------------------------
#define SPB 4   // samples per block

__global__ void __launch_bounds__(256, 3) gating_kernel(
    const int* __restrict__ n_exp,
    float* __restrict__ out_logits,
    float* __restrict__ out_gates)
{
    __shared__ float sred[8][8];       // [warp][expert]
    __shared__ float sredG[32][36];    // [warp*4+group][pair]
    __shared__ float smax[K_], sZ[K_], sG[K_ * K_], sgate[K_];

    const int tid = threadIdx.x;
    const int w = tid >> 5, lane = tid & 31;
    const bool act = (tid < 250);
    const int c = tid * 4;
    const int grp = lane >> 3;         // 0..3 (8-lane group within warp)

    for (int s = 0; s < SPB; s++) {
        const int b = blockIdx.x * SPB + s;

        const float* lrow = g_logits + (size_t)b * K_ * CP_;
        float4 lg[K_];
#pragma unroll
        for (int k = 0; k < K_; k++)
            lg[k] = act ? *(const float4*)(lrow + (size_t)k * CP_ + c)
                        : make_float4(-INFINITY, -INFINITY, -INFINITY, -INFINITY);

        // 1) per-expert max
#pragma unroll
        for (int k = 0; k < K_; k++) {
            float m = fmaxf(fmaxf(lg[k].x, lg[k].y), fmaxf(lg[k].z, lg[k].w));
#pragma unroll
            for (int o = 16; o > 0; o >>= 1) m = fmaxf(m, __shfl_xor_sync(0xffffffffu, m, o));
            if (lane == 0) sred[w][k] = m;
        }
        __syncthreads();
        if (tid < K_) {
            float m = sred[0][tid];
#pragma unroll
            for (int j = 1; j < 8; j++) m = fmaxf(m, sred[j][tid]);
            smax[tid] = m;
        }
        __syncthreads();

        // 2) exp + sum partials; gram partials (3-step group reduce)
        float se[K_][4];
#pragma unroll
        for (int k = 0; k < K_; k++) {
            float m = smax[k];
            se[k][0] = __expf(lg[k].x - m);
            se[k][1] = __expf(lg[k].y - m);
            se[k][2] = __expf(lg[k].z - m);
            se[k][3] = __expf(lg[k].w - m);
            float z = se[k][0] + se[k][1] + se[k][2] + se[k][3];
#pragma unroll
            for (int o = 16; o > 0; o >>= 1) z += __shfl_xor_sync(0xffffffffu, z, o);
            if (lane == 0) sred[w][k] = z;
        }
        {
            int p = 0;
#pragma unroll
            for (int i = 0; i < K_; i++)
#pragma unroll
                for (int j = i; j < K_; j++) {
                    float sacc = se[i][0] * se[j][0] + se[i][1] * se[j][1] +
                                 se[i][2] * se[j][2] + se[i][3] * se[j][3];
                    // reduce within 8-lane groups (offsets 1,2,4)
                    sacc += __shfl_xor_sync(0xffffffffu, sacc, 1);
                    sacc += __shfl_xor_sync(0xffffffffu, sacc, 2);
                    sacc += __shfl_xor_sync(0xffffffffu, sacc, 4);
                    if ((lane & 7) == 0) sredG[w * 4 + grp][p] = sacc;
                    p++;
                }
        }
        __syncthreads();
        if (tid < K_) {
            float z = 0.0f;
#pragma unroll
            for (int j = 0; j < 8; j++) z += sred[j][tid];
            sZ[tid] = z;
        }
        if (tid >= 32 && tid < 68) {
            int p = tid - 32;
            float ssum = 0.0f;
#pragma unroll
            for (int j = 0; j < 32; j++) ssum += sredG[j][p];
            int i = 0, q = p;
            while (q >= K_ - i) { q -= (K_ - i); i++; }
            int jj = i + q;
            sG[i * K_ + jj] = ssum;
            sG[jj * K_ + i] = ssum;
        }
        __syncthreads();

        // 3) greedy selection — lanes 0..7 of warp 0
        if (tid < 8) {
            const unsigned MSK = 0xFFu;
            const int i = tid;
            float zz = sZ[i];
            float gii = sG[i * K_ + i] / (zz * zz);
            float nrmv = sqrtf(gii) + EPSV;
            float confv = 1.0f / zz;
            float Srow[K_];
#pragma unroll
            for (int j = 0; j < K_; j++) {
                float nrmj = __shfl_sync(MSK, nrmv, j, 8);
                float zj = __shfl_sync(MSK, zz, j, 8);
                Srow[j] = (sG[i * K_ + j] / (zz * zj)) / (nrmv * nrmj);
            }

            float bv = confv; int bi = i;
#pragma unroll
            for (int o = 4; o > 0; o >>= 1) {
                float ov = __shfl_down_sync(MSK, bv, o, 8);
                int oi = __shfl_down_sync(MSK, bi, o, 8);
                if (ov > bv || (ov == bv && oi < bi)) { bv = ov; bi = oi; }
            }
            bi = __shfl_sync(MSK, bi, 0, 8);
            unsigned selMask = 1u << bi;

            int n = n_exp[b];
            for (int t = 1; t < K_; t++) {
                float dist;
                if (selMask & (1u << i)) dist = -INFINITY;
                else {
                    float ms = -INFINITY;
#pragma unroll
                    for (int j = 0; j < K_; j++)
                        if (selMask & (1u << j)) ms = fmaxf(ms, Srow[j]);
                    dist = 1.0f - ms;
                }
                float av = dist; int ai = i;
#pragma unroll
                for (int o = 4; o > 0; o >>= 1) {
                    float ov = __shfl_down_sync(MSK, av, o, 8);
                    int oi = __shfl_down_sync(MSK, ai, o, 8);
                    if (ov > av || (ov == av && oi < ai)) { av = ov; ai = oi; }
                }
                ai = __shfl_sync(MSK, ai, 0, 8);
                if (t < n) selMask |= 1u << ai;
            }

            float gl = ((selMask >> i) & 1u) ? confv / TEMPV : NEGV / TEMPV;
            float gm = gl;
#pragma unroll
            for (int o = 4; o > 0; o >>= 1) gm = fmaxf(gm, __shfl_xor_sync(MSK, gm, o, 8));
            float ge = __expf(gl - gm);
            float gs = ge;
#pragma unroll
            for (int o = 4; o > 0; o >>= 1) gs += __shfl_xor_sync(MSK, gs, o, 8);
            sgate[i] = ge / gs;
        }
        __syncthreads();

        // 4) gated combine straight from registers
        if (act) {
            float4 a4 = make_float4(0.f, 0.f, 0.f, 0.f);
#pragma unroll
            for (int k = 0; k < K_; k++) {
                float g = sgate[k];
                a4.x += g * lg[k].x; a4.y += g * lg[k].y;
                a4.z += g * lg[k].z; a4.w += g * lg[k].w;
            }
            *(float4*)(out_logits + (size_t)b * C_ + c) = a4;
        }
        if (tid < K_) out_gates[(size_t)b * K_ + tid] = sgate[tid];
        __syncthreads();
    }
}

// ---------------------------------------------------------------------------
extern "C" void kernel_launch(void* const* d_in, const int* in_sizes, int n_in,
                              void* d_out, int out_size)
{
    const float* z    = (const float*)d_in[0];
    const int*   nexp = (const int*)d_in[1];
    const float* W1   = (const float*)d_in[2];
    const float* b1   = (const float*)d_in[3];
    const float* W2   = (const float*)d_in[4];
    const float* b2   = (const float*)d_in[5];
    float* out = (float*)d_out;

    __half *z0, *z1, *w10, *w11, *w20, *w21, *h0, *h1;
    float* lg;
    cudaGetSymbolAddress((void**)&z0, g_z0);   cudaGetSymbolAddress((void**)&z1, g_z1);
    cudaGetSymbolAddress((void**)&w10, g_w1t0); cudaGetSymbolAddress((void**)&w11, g_w1t1);
    cudaGetSymbolAddress((void**)&w20, g_w2t0); cudaGetSymbolAddress((void**)&w21, g_w2t1);
    cudaGetSymbolAddress((void**)&h0, g_h0);   cudaGetSymbolAddress((void**)&h1, g_h1);
    cudaGetSymbolAddress((void**)&lg, g_logits);

    cudaFuncSetAttribute(tc_gemm<true>,  cudaFuncAttributeMaxDynamicSharedMemorySize, NSTAGE * STAGE_B);
    cudaFuncSetAttribute(tc_gemm<false>, cudaFuncAttributeMaxDynamicSharedMemorySize, NSTAGE * STAGE_B);

    // merged input conversions (z, W1, W2 in one launch)
    convert_all_kernel<<<NB_Z + NB_W1 + NB_W2, 256>>>(
        z, W1, W2, z0, z1, w10, w11, w20, w21);

    // GEMM1: h = relu(z @ W1 + b1), re-split into 2 fp16 limbs
    tc_gemm<true><<<dim3(D_ / 128, B_ / 128, K_), 256, NSTAGE * STAGE_B>>>(
        z0, z1, 0LL,
        w10, w11, (long long)D_ * D_,
        b1, D_, D_, nullptr, 0, h0, h1);

    // GEMM2: logits = h @ W2 + b2 (fp32, padded to CP_)
    tc_gemm<false><<<dim3(CP_ / 128, B_ / 128, K_), 256, NSTAGE * STAGE_B>>>(
        h0, h1, (long long)B_ * D_,
        w20, w21, (long long)CP_ * D_,
        b2, C_, C_, lg, CP_, nullptr, nullptr);

    // gating + combine
    gating_kernel<<<B_ / SPB, 256>>>(nexp, out, out + (size_t)B_ * C_);
}

// round 14
// speedup vs baseline: 1.0290x; 1.0290x over previous
#include <cuda_runtime.h>
#include <cuda_fp16.h>
#include <cstdint>
#include <math.h>

#define B_ 8192
#define D_ 512
#define C_ 1000
#define CP_ 1024
#define K_ 8
#define EPSV 1e-8f
#define TEMPV 0.2f
#define NEGV -10000.0f

// ---------------------------------------------------------------------------
// Scratch (__device__ globals)
// ---------------------------------------------------------------------------
__device__ __half g_z0[(size_t)B_ * D_];
__device__ __half g_z1[(size_t)B_ * D_];
__device__ __half g_w1t0[(size_t)K_ * D_ * D_];
__device__ __half g_w1t1[(size_t)K_ * D_ * D_];
__device__ __half g_w2t0[(size_t)K_ * CP_ * D_];
__device__ __half g_w2t1[(size_t)K_ * CP_ * D_];
__device__ __half g_h0[(size_t)K_ * B_ * D_];
__device__ __half g_h1[(size_t)K_ * B_ * D_];
__device__ float g_logits[(size_t)B_ * K_ * CP_];

// ---------------------------------------------------------------------------
// PTX helpers
// ---------------------------------------------------------------------------
__device__ __forceinline__ uint32_t smem_u32(const void* p) {
    uint32_t a;
    asm("{ .reg .u64 t; cvta.to.shared.u64 t, %1; cvt.u32.u64 %0, t; }" : "=r"(a) : "l"(p));
    return a;
}
__device__ __forceinline__ void cp_async16(uint32_t s, const void* g) {
    asm volatile("cp.async.cg.shared.global [%0], [%1], 16;" :: "r"(s), "l"(g));
}
__device__ __forceinline__ void cp_commit() { asm volatile("cp.async.commit_group;"); }
template <int N>
__device__ __forceinline__ void cp_wait() { asm volatile("cp.async.wait_group %0;" :: "n"(N)); }

__device__ __forceinline__ void ldsm4(uint32_t* r, uint32_t addr) {
    asm volatile("ldmatrix.sync.aligned.m8n8.x4.shared.b16 {%0,%1,%2,%3}, [%4];"
                 : "=r"(r[0]), "=r"(r[1]), "=r"(r[2]), "=r"(r[3]) : "r"(addr));
}
__device__ __forceinline__ void mma16816(float* c, const uint32_t* a, uint32_t b0, uint32_t b1) {
    asm volatile(
        "mma.sync.aligned.m16n8k16.row.col.f32.f16.f16.f32 "
        "{%0,%1,%2,%3}, {%4,%5,%6,%7}, {%8,%9}, {%0,%1,%2,%3};"
        : "+f"(c[0]), "+f"(c[1]), "+f"(c[2]), "+f"(c[3])
        : "r"(a[0]), "r"(a[1]), "r"(a[2]), "r"(a[3]), "r"(b0), "r"(b1));
}

// 2-limb fp16 split: x = a + b + O(2^-22 |x|)
__device__ __forceinline__ void split2(float x, __half& a, __half& b) {
    a = __float2half_rn(x);
    b = __float2half_rn(x - __half2float(a));
}

// ---------------------------------------------------------------------------
// Merged conversion kernel (one launch: z split + W1/W2 transpose-split)
// ---------------------------------------------------------------------------
#define NB_Z  (B_ * D_ / 4 / 256)            // 4096
#define NB_W1 ((D_ / 32) * (D_ / 32) * K_)   // 2048
#define NB_W2 ((CP_ / 32) * (D_ / 32) * K_)  // 4096

__device__ __forceinline__ void trsplit_body(
    const float* __restrict__ in, __half* __restrict__ o0, __half* __restrict__ o1,
    int Nin, int Npad, int bx, int by, int k, int tid)
{
    __shared__ float t[32][33];
    const int n0 = bx * 32, d0 = by * 32;
    const int tx = tid & 31, ty = tid >> 5;
    const float* src = in + (size_t)k * D_ * Nin;
#pragma unroll
    for (int r = 0; r < 4; r++) {
        int d = d0 + ty + r * 8, n = n0 + tx;
        t[ty + r * 8][tx] = (n < Nin) ? src[(size_t)d * Nin + n] : 0.0f;
    }
    __syncthreads();
    size_t obase = (size_t)k * Npad * D_;
#pragma unroll
    for (int r = 0; r < 4; r++) {
        int nl = ty + r * 8;
        float v = t[tx][nl];
        __half a, b;
        split2(v, a, b);
        size_t oi = obase + (size_t)(n0 + nl) * D_ + d0 + tx;
        o0[oi] = a; o1[oi] = b;
    }
}

__global__ void __launch_bounds__(256) convert_all_kernel(
    const float* __restrict__ z, const float* __restrict__ W1,
    const float* __restrict__ W2,
    __half* __restrict__ z0, __half* __restrict__ z1,
    __half* __restrict__ w10, __half* __restrict__ w11,
    __half* __restrict__ w20, __half* __restrict__ w21)
{
    const int blk = blockIdx.x;
    const int tid = threadIdx.x;
    if (blk < NB_Z) {
        int i = blk * 256 + tid;
        float4 v = ((const float4*)z)[i];
        __half a0, b0, a1, b1, a2, b2, a3, b3;
        split2(v.x, a0, b0); split2(v.y, a1, b1);
        split2(v.z, a2, b2); split2(v.w, a3, b3);
        ((__half2*)z0)[i * 2]     = __half2(a0, a1);
        ((__half2*)z0)[i * 2 + 1] = __half2(a2, a3);
        ((__half2*)z1)[i * 2]     = __half2(b0, b1);
        ((__half2*)z1)[i * 2 + 1] = __half2(b2, b3);
    } else if (blk < NB_Z + NB_W1) {
        int r = blk - NB_Z;
        int bx = r & 15; r >>= 4;
        int by = r & 15; r >>= 4;
        trsplit_body(W1, w10, w11, D_, D_, bx, by, r, tid);
    } else {
        int r = blk - NB_Z - NB_W1;
        int bx = r & 31; r >>= 5;
        int by = r & 15; r >>= 4;
        trsplit_body(W2, w20, w21, C_, CP_, bx, by, r, tid);
    }
}

// ---------------------------------------------------------------------------
// HMMA fp16 GEMM with 3-product 2-limb split. (unchanged — proven)
// ---------------------------------------------------------------------------
#define TILE_B 8192
#define STAGE_B (4 * TILE_B)
#define NSTAGE 3
#define NCHUNK 16
#define EPI_PITCH_H 272
#define EPI_PITCH_F 528

template <bool SPLIT>
__global__ void __launch_bounds__(256, 2) tc_gemm(
    const __half* __restrict__ A0, const __half* __restrict__ A1, long long aStr,
    const __half* __restrict__ B0, const __half* __restrict__ B1, long long bStr,
    const float* __restrict__ bias, int biasStr, int Nreal,
    float* __restrict__ outF, int outLd,
    __half* __restrict__ O0, __half* __restrict__ O1)
{
    extern __shared__ __align__(16) char dsm[];
    const uint32_t sbase = smem_u32(dsm);

    const int tid = threadIdx.x;
    const int warp = tid >> 5, lane = tid & 31;
    const int bz = blockIdx.z;
    const int m0 = blockIdx.y * 128, n0 = blockIdx.x * 128;
    const int warpM = (warp >> 2) * 64;
    const int warpN = (warp & 3) * 32;

    const char* gp[4];
    gp[0] = (const char*)A0 + ((size_t)bz * aStr + (size_t)m0 * D_) * 2;
    gp[1] = (const char*)A1 + ((size_t)bz * aStr + (size_t)m0 * D_) * 2;
    gp[2] = (const char*)B0 + ((size_t)bz * bStr + (size_t)n0 * D_) * 2;
    gp[3] = (const char*)B1 + ((size_t)bz * bStr + (size_t)n0 * D_) * 2;

    const int ldRow0 = tid >> 2, ldC0 = tid & 3;
    const int ldRow1 = (tid + 256) >> 2, ldC1 = (tid + 256) & 3;
    const uint32_t ldDst0 = (uint32_t)ldRow0 * 64 + (uint32_t)((ldC0 ^ ((ldRow0 >> 1) & 3)) << 4);
    const uint32_t ldDst1 = (uint32_t)ldRow1 * 64 + (uint32_t)((ldC1 ^ ((ldRow1 >> 1) & 3)) << 4);
    const size_t ldSrc0 = (size_t)ldRow0 * 1024 + ldC0 * 16;
    const size_t ldSrc1 = (size_t)ldRow1 * 1024 + ldC1 * 16;

    auto load_stage = [&](int kk, int buf) {
        const size_t koff = (size_t)kk * 64;
#pragma unroll
        for (int t = 0; t < 4; t++) {
            uint32_t sb = sbase + buf * STAGE_B + t * TILE_B;
            const char* g = gp[t] + koff;
            cp_async16(sb + ldDst0, g + ldSrc0);
            cp_async16(sb + ldDst1, g + ldSrc1);
        }
        cp_commit();
    };

    float acc[4][4][4];
#pragma unroll
    for (int i = 0; i < 4; i++)
#pragma unroll
        for (int j = 0; j < 4; j++)
#pragma unroll
            for (int r = 0; r < 4; r++) acc[i][j][r] = 0.0f;

    load_stage(0, 0);
    load_stage(1, 1);

    const int rowA = warpM + (lane & 15);
    const uint32_t swA = (uint32_t)((rowA >> 1) & 3);
    const uint32_t cA = (uint32_t)(lane >> 4);
    const uint32_t aBase = (uint32_t)rowA * 64;

    const int rowB = warpN + (lane & 7) + ((lane >> 4) & 1) * 8;
    const uint32_t swB = (uint32_t)((rowB >> 1) & 3);
    const uint32_t cB = (uint32_t)((lane >> 3) & 1);
    const uint32_t bBase = (uint32_t)rowB * 64;

    for (int kk = 0; kk < NCHUNK; kk++) {
        if (kk == NCHUNK - 1) cp_wait<0>(); else cp_wait<1>();
        __syncthreads();
        if (kk + 2 < NCHUNK) load_stage(kk + 2, (kk + 2) % NSTAGE);

        const uint32_t sb = sbase + (kk % NSTAGE) * STAGE_B;

#pragma unroll
        for (int ks = 0; ks < 2; ks++) {
            const uint32_t aOff = aBase + (((ks * 2 + cA) ^ swA) << 4);
            const uint32_t bOff = bBase + (((ks * 2 + cB) ^ swB) << 4);
            uint32_t a0f[4][4], b0f[2][4];
#pragma unroll
            for (int i = 0; i < 4; i++)
                ldsm4(a0f[i], sb + 0 * TILE_B + aOff + i * 1024);
#pragma unroll
            for (int jp = 0; jp < 2; jp++)
                ldsm4(b0f[jp], sb + 2 * TILE_B + bOff + jp * 1024);
#pragma unroll
            for (int i = 0; i < 4; i++)
#pragma unroll
                for (int j = 0; j < 4; j++)
                    mma16816(acc[i][j], a0f[i], b0f[j >> 1][(j & 1) * 2],
                             b0f[j >> 1][(j & 1) * 2 + 1]);
            {
                uint32_t b1f[2][4];
#pragma unroll
                for (int jp = 0; jp < 2; jp++)
                    ldsm4(b1f[jp], sb + 3 * TILE_B + bOff + jp * 1024);
#pragma unroll
                for (int i = 0; i < 4; i++)
#pragma unroll
                    for (int j = 0; j < 4; j++)
                        mma16816(acc[i][j], a0f[i], b1f[j >> 1][(j & 1) * 2],
                                 b1f[j >> 1][(j & 1) * 2 + 1]);
            }
            {
                uint32_t a1f[4][4];
#pragma unroll
                for (int i = 0; i < 4; i++)
                    ldsm4(a1f[i], sb + 1 * TILE_B + aOff + i * 1024);
#pragma unroll
                for (int i = 0; i < 4; i++)
#pragma unroll
                    for (int j = 0; j < 4; j++)
                        mma16816(acc[i][j], a1f[i], b0f[j >> 1][(j & 1) * 2],
                                 b0f[j >> 1][(j & 1) * 2 + 1]);
            }
        }
    }

    // ---------------- epilogue: smem-staged, coalesced global writes --------
    __syncthreads();

    const int rBase = warpM + (lane >> 2);
    const int cBaseH = warpN + (lane & 3) * 2;

    float bj[4][2];
#pragma unroll
    for (int j = 0; j < 4; j++)
#pragma unroll
        for (int t = 0; t < 2; t++) {
            int n = n0 + cBaseH + j * 8 + t;
            bj[j][t] = (SPLIT || n < Nreal) ? bias[bz * biasStr + n] : 0.0f;
        }

    if (SPLIT) {
#pragma unroll
        for (int i = 0; i < 4; i++)
#pragma unroll
            for (int j = 0; j < 4; j++)
#pragma unroll
                for (int half = 0; half < 2; half++) {
                    const int r = rBase + i * 16 + half * 8;
                    const int c = cBaseH + j * 8;
                    float v0 = fmaxf(acc[i][j][half * 2]     + bj[j][0], 0.0f);
                    float v1 = fmaxf(acc[i][j][half * 2 + 1] + bj[j][1], 0.0f);
                    __half a0, b0, a1, b1;
                    split2(v0, a0, b0);
                    split2(v1, a1, b1);
                    *(__half2*)(dsm + r * EPI_PITCH_H + c * 2) = __half2(a0, a1);
                    *(__half2*)(dsm + 128 * EPI_PITCH_H + r * EPI_PITCH_H + c * 2) = __half2(b0, b1);
                }
        __syncthreads();
#pragma unroll
        for (int it = 0; it < 8; it++) {
            int idx = tid + it * 256;
            int r = idx >> 4, c16 = idx & 15;
            float4 w0 = *(const float4*)(dsm + r * EPI_PITCH_H + c16 * 16);
            float4 w1 = *(const float4*)(dsm + 128 * EPI_PITCH_H + r * EPI_PITCH_H + c16 * 16);
            size_t gb = ((size_t)bz * B_ + m0 + r) * D_ + n0 + c16 * 8;
            *(float4*)&O0[gb] = w0;
            *(float4*)&O1[gb] = w1;
        }
    } else {
#pragma unroll
        for (int i = 0; i < 4; i++)
#pragma unroll
            for (int j = 0; j < 4; j++)
#pragma unroll
                for (int half = 0; half < 2; half++) {
                    const int r = rBase + i * 16 + half * 8;
                    const int c = cBaseH + j * 8;
                    float2 vv = make_float2(acc[i][j][half * 2]     + bj[j][0],
                                            acc[i][j][half * 2 + 1] + bj[j][1]);
                    *(float2*)(dsm + r * EPI_PITCH_F + c * 4) = vv;
                }
        __syncthreads();
#pragma unroll
        for (int it = 0; it < 16; it++) {
            int idx = tid + it * 256;
            int r = idx >> 5, c4 = idx & 31;
            float4 w = *(const float4*)(dsm + r * EPI_PITCH_F + c4 * 16);
            *(float4*)&outF[((size_t)(m0 + r) * K_ + bz) * outLd + n0 + c4 * 4] = w;
        }
    }
}

// ---------------------------------------------------------------------------
// Gating kernel v5 — R12 structure (grid B_, 5-step Gram), but logits are
// stashed in smem instead of registers -> ~56 regs -> 4 CTAs/SM.
// ---------------------------------------------------------------------------
__global__ void __launch_bounds__(256, 4) gating_kernel(
    const int* __restrict__ n_exp,
    float* __restrict__ out_logits,
    float* __restrict__ out_gates)
{
    __shared__ float4 slg[K_][256];    // 32 KB: [expert][thread]
    __shared__ float sred[8][8];       // [warp][expert]
    __shared__ float sredG[8][36];     // [warp][pair]
    __shared__ float smax[K_], sZ[K_], sG[K_ * K_], sgate[K_];

    const int b = blockIdx.x, tid = threadIdx.x;
    const int w = tid >> 5, lane = tid & 31;
    const bool act = (tid < 250);
    const int c = tid * 4;

    const float* lrow = g_logits + (size_t)b * K_ * CP_;

    // load -> stash to smem; per-expert max partials
#pragma unroll
    for (int k = 0; k < K_; k++) {
        float4 v = act ? *(const float4*)(lrow + (size_t)k * CP_ + c)
                       : make_float4(-INFINITY, -INFINITY, -INFINITY, -INFINITY);
        slg[k][tid] = v;
        float m = fmaxf(fmaxf(v.x, v.y), fmaxf(v.z, v.w));
#pragma unroll
        for (int o = 16; o > 0; o >>= 1) m = fmaxf(m, __shfl_xor_sync(0xffffffffu, m, o));
        if (lane == 0) sred[w][k] = m;
    }
    __syncthreads();
    if (tid < K_) {
        float m = sred[0][tid];
#pragma unroll
        for (int j = 1; j < 8; j++) m = fmaxf(m, sred[j][tid]);
        smax[tid] = m;
    }
    __syncthreads();

    // exp + sum partials; gram partials (se register-resident)
    float se[K_][4];
#pragma unroll
    for (int k = 0; k < K_; k++) {
        float m = smax[k];
        float4 v = slg[k][tid];
        se[k][0] = __expf(v.x - m);
        se[k][1] = __expf(v.y - m);
        se[k][2] = __expf(v.z - m);
        se[k][3] = __expf(v.w - m);
        float z = se[k][0] + se[k][1] + se[k][2] + se[k][3];
#pragma unroll
        for (int o = 16; o > 0; o >>= 1) z += __shfl_xor_sync(0xffffffffu, z, o);
        if (lane == 0) sred[w][k] = z;
    }
    {
        int p = 0;
#pragma unroll
        for (int i = 0; i < K_; i++)
#pragma unroll
            for (int j = i; j < K_; j++) {
                float s = se[i][0] * se[j][0] + se[i][1] * se[j][1] +
                          se[i][2] * se[j][2] + se[i][3] * se[j][3];
#pragma unroll
                for (int o = 16; o > 0; o >>= 1) s += __shfl_xor_sync(0xffffffffu, s, o);
                if (lane == 0) sredG[w][p] = s;
                p++;
            }
    }
    __syncthreads();
    if (tid < K_) {
        float z = 0.0f;
#pragma unroll
        for (int j = 0; j < 8; j++) z += sred[j][tid];
        sZ[tid] = z;
    }
    __syncthreads();
    if (tid < 36) {
        float s = 0.0f;
#pragma unroll
        for (int j = 0; j < 8; j++) s += sredG[j][tid];
        int i = 0, q = tid;
        while (q >= K_ - i) { q -= (K_ - i); i++; }
        int jj = i + q;
        float g = s / (sZ[i] * sZ[jj]);
        sG[i * K_ + jj] = g;
        sG[jj * K_ + i] = g;
    }
    __syncthreads();

    // greedy selection — lanes 0..7 of warp 0
    if (tid < 8) {
        const unsigned MSK = 0xFFu;
        const int i = tid;
        float nrmv = sqrtf(sG[i * K_ + i]) + EPSV;
        float confv = 1.0f / sZ[i];
        float Srow[K_];
#pragma unroll
        for (int j = 0; j < K_; j++) {
            float nrmj = __shfl_sync(MSK, nrmv, j, 8);
            Srow[j] = sG[i * K_ + j] / (nrmv * nrmj);
        }

        float bv = confv; int bi = i;
#pragma unroll
        for (int o = 4; o > 0; o >>= 1) {
            float ov = __shfl_down_sync(MSK, bv, o, 8);
            int oi = __shfl_down_sync(MSK, bi, o, 8);
            if (ov > bv || (ov == bv && oi < bi)) { bv = ov; bi = oi; }
        }
        bi = __shfl_sync(MSK, bi, 0, 8);
        unsigned selMask = 1u << bi;

        int n = n_exp[b];
        for (int t = 1; t < K_; t++) {
            float dist;
            if (selMask & (1u << i)) dist = -INFINITY;
            else {
                float ms = -INFINITY;
#pragma unroll
                for (int j = 0; j < K_; j++)
                    if (selMask & (1u << j)) ms = fmaxf(ms, Srow[j]);
                dist = 1.0f - ms;
            }
            float av = dist; int ai = i;
#pragma unroll
            for (int o = 4; o > 0; o >>= 1) {
                float ov = __shfl_down_sync(MSK, av, o, 8);
                int oi = __shfl_down_sync(MSK, ai, o, 8);
                if (ov > av || (ov == av && oi < ai)) { av = ov; ai = oi; }
            }
            ai = __shfl_sync(MSK, ai, 0, 8);
            if (t < n) selMask |= 1u << ai;
        }

        float gl = ((selMask >> i) & 1u) ? confv / TEMPV : NEGV / TEMPV;
        float gm = gl;
#pragma unroll
        for (int o = 4; o > 0; o >>= 1) gm = fmaxf(gm, __shfl_xor_sync(MSK, gm, o, 8));
        float ge = __expf(gl - gm);
        float gs = ge;
#pragma unroll
        for (int o = 4; o > 0; o >>= 1) gs += __shfl_xor_sync(MSK, gs, o, 8);
        sgate[i] = ge / gs;
    }
    __syncthreads();

    // gated combine (logits re-read from smem)
    if (act) {
        float4 a4 = make_float4(0.f, 0.f, 0.f, 0.f);
#pragma unroll
        for (int k = 0; k < K_; k++) {
            float g = sgate[k];
            float4 v = slg[k][tid];
            a4.x += g * v.x; a4.y += g * v.y;
            a4.z += g * v.z; a4.w += g * v.w;
        }
        *(float4*)(out_logits + (size_t)b * C_ + c) = a4;
    }
    if (tid < K_) out_gates[(size_t)b * K_ + tid] = sgate[tid];
}

// ---------------------------------------------------------------------------
extern "C" void kernel_launch(void* const* d_in, const int* in_sizes, int n_in,
                              void* d_out, int out_size)
{
    const float* z    = (const float*)d_in[0];
    const int*   nexp = (const int*)d_in[1];
    const float* W1   = (const float*)d_in[2];
    const float* b1   = (const float*)d_in[3];
    const float* W2   = (const float*)d_in[4];
    const float* b2   = (const float*)d_in[5];
    float* out = (float*)d_out;

    __half *z0, *z1, *w10, *w11, *w20, *w21, *h0, *h1;
    float* lg;
    cudaGetSymbolAddress((void**)&z0, g_z0);   cudaGetSymbolAddress((void**)&z1, g_z1);
    cudaGetSymbolAddress((void**)&w10, g_w1t0); cudaGetSymbolAddress((void**)&w11, g_w1t1);
    cudaGetSymbolAddress((void**)&w20, g_w2t0); cudaGetSymbolAddress((void**)&w21, g_w2t1);
    cudaGetSymbolAddress((void**)&h0, g_h0);   cudaGetSymbolAddress((void**)&h1, g_h1);
    cudaGetSymbolAddress((void**)&lg, g_logits);

    cudaFuncSetAttribute(tc_gemm<true>,  cudaFuncAttributeMaxDynamicSharedMemorySize, NSTAGE * STAGE_B);
    cudaFuncSetAttribute(tc_gemm<false>, cudaFuncAttributeMaxDynamicSharedMemorySize, NSTAGE * STAGE_B);

    // merged input conversions (z, W1, W2 in one launch)
    convert_all_kernel<<<NB_Z + NB_W1 + NB_W2, 256>>>(
        z, W1, W2, z0, z1, w10, w11, w20, w21);

    // GEMM1: h = relu(z @ W1 + b1), re-split into 2 fp16 limbs
    tc_gemm<true><<<dim3(D_ / 128, B_ / 128, K_), 256, NSTAGE * STAGE_B>>>(
        z0, z1, 0LL,
        w10, w11, (long long)D_ * D_,
        b1, D_, D_, nullptr, 0, h0, h1);

    // GEMM2: logits = h @ W2 + b2 (fp32, padded to CP_)
    tc_gemm<false><<<dim3(CP_ / 128, B_ / 128, K_), 256, NSTAGE * STAGE_B>>>(
        h0, h1, (long long)B_ * D_,
        w20, w21, (long long)CP_ * D_,
        b2, C_, C_, lg, CP_, nullptr, nullptr);

    // gating + combine
    gating_kernel<<<B_, 256>>>(nexp, out, out + (size_t)B_ * C_);
}

// round 15
// speedup vs baseline: 1.0293x; 1.0003x over previous
#include <cuda_runtime.h>
#include <cuda_fp16.h>
#include <cstdint>
#include <math.h>

#define B_ 8192
#define D_ 512
#define C_ 1000
#define CP_ 1024
#define K_ 8
#define EPSV 1e-8f
#define TEMPV 0.2f
#define NEGV -10000.0f

// ---------------------------------------------------------------------------
// Scratch (__device__ globals)
// ---------------------------------------------------------------------------
__device__ __half g_z0[(size_t)B_ * D_];
__device__ __half g_z1[(size_t)B_ * D_];
__device__ __half g_w1t0[(size_t)K_ * D_ * D_];
__device__ __half g_w1t1[(size_t)K_ * D_ * D_];
__device__ __half g_w2t0[(size_t)K_ * CP_ * D_];
__device__ __half g_w2t1[(size_t)K_ * CP_ * D_];
__device__ __half g_h0[(size_t)K_ * B_ * D_];
__device__ __half g_h1[(size_t)K_ * B_ * D_];
__device__ float g_logits[(size_t)B_ * K_ * CP_];

// ---------------------------------------------------------------------------
// PTX helpers
// ---------------------------------------------------------------------------
__device__ __forceinline__ uint32_t smem_u32(const void* p) {
    uint32_t a;
    asm("{ .reg .u64 t; cvta.to.shared.u64 t, %1; cvt.u32.u64 %0, t; }" : "=r"(a) : "l"(p));
    return a;
}
__device__ __forceinline__ void cp_async16(uint32_t s, const void* g) {
    asm volatile("cp.async.cg.shared.global [%0], [%1], 16;" :: "r"(s), "l"(g));
}
__device__ __forceinline__ void cp_commit() { asm volatile("cp.async.commit_group;"); }
template <int N>
__device__ __forceinline__ void cp_wait() { asm volatile("cp.async.wait_group %0;" :: "n"(N)); }

__device__ __forceinline__ void ldsm4(uint32_t* r, uint32_t addr) {
    asm volatile("ldmatrix.sync.aligned.m8n8.x4.shared.b16 {%0,%1,%2,%3}, [%4];"
                 : "=r"(r[0]), "=r"(r[1]), "=r"(r[2]), "=r"(r[3]) : "r"(addr));
}
__device__ __forceinline__ void mma16816(float* c, const uint32_t* a, uint32_t b0, uint32_t b1) {
    asm volatile(
        "mma.sync.aligned.m16n8k16.row.col.f32.f16.f16.f32 "
        "{%0,%1,%2,%3}, {%4,%5,%6,%7}, {%8,%9}, {%0,%1,%2,%3};"
        : "+f"(c[0]), "+f"(c[1]), "+f"(c[2]), "+f"(c[3])
        : "r"(a[0]), "r"(a[1]), "r"(a[2]), "r"(a[3]), "r"(b0), "r"(b1));
}

// 2-limb fp16 split: x = a + b + O(2^-22 |x|)
__device__ __forceinline__ void split2(float x, __half& a, __half& b) {
    a = __float2half_rn(x);
    b = __float2half_rn(x - __half2float(a));
}

// ---------------------------------------------------------------------------
// Merged conversion kernel (one launch: z split + W1/W2 transpose-split)
// ---------------------------------------------------------------------------
#define NB_Z  (B_ * D_ / 4 / 256)            // 4096
#define NB_W1 ((D_ / 32) * (D_ / 32) * K_)   // 2048
#define NB_W2 ((CP_ / 32) * (D_ / 32) * K_)  // 4096

__device__ __forceinline__ void trsplit_body(
    const float* __restrict__ in, __half* __restrict__ o0, __half* __restrict__ o1,
    int Nin, int Npad, int bx, int by, int k, int tid)
{
    __shared__ float t[32][33];
    const int n0 = bx * 32, d0 = by * 32;
    const int tx = tid & 31, ty = tid >> 5;
    const float* src = in + (size_t)k * D_ * Nin;
#pragma unroll
    for (int r = 0; r < 4; r++) {
        int d = d0 + ty + r * 8, n = n0 + tx;
        t[ty + r * 8][tx] = (n < Nin) ? src[(size_t)d * Nin + n] : 0.0f;
    }
    __syncthreads();
    size_t obase = (size_t)k * Npad * D_;
#pragma unroll
    for (int r = 0; r < 4; r++) {
        int nl = ty + r * 8;
        float v = t[tx][nl];
        __half a, b;
        split2(v, a, b);
        size_t oi = obase + (size_t)(n0 + nl) * D_ + d0 + tx;
        o0[oi] = a; o1[oi] = b;
    }
}

__global__ void __launch_bounds__(256) convert_all_kernel(
    const float* __restrict__ z, const float* __restrict__ W1,
    const float* __restrict__ W2,
    __half* __restrict__ z0, __half* __restrict__ z1,
    __half* __restrict__ w10, __half* __restrict__ w11,
    __half* __restrict__ w20, __half* __restrict__ w21)
{
    const int blk = blockIdx.x;
    const int tid = threadIdx.x;
    if (blk < NB_Z) {
        int i = blk * 256 + tid;
        float4 v = ((const float4*)z)[i];
        __half a0, b0, a1, b1, a2, b2, a3, b3;
        split2(v.x, a0, b0); split2(v.y, a1, b1);
        split2(v.z, a2, b2); split2(v.w, a3, b3);
        ((__half2*)z0)[i * 2]     = __half2(a0, a1);
        ((__half2*)z0)[i * 2 + 1] = __half2(a2, a3);
        ((__half2*)z1)[i * 2]     = __half2(b0, b1);
        ((__half2*)z1)[i * 2 + 1] = __half2(b2, b3);
    } else if (blk < NB_Z + NB_W1) {
        int r = blk - NB_Z;
        int bx = r & 15; r >>= 4;
        int by = r & 15; r >>= 4;
        trsplit_body(W1, w10, w11, D_, D_, bx, by, r, tid);
    } else {
        int r = blk - NB_Z - NB_W1;
        int bx = r & 31; r >>= 5;
        int by = r & 15; r >>= 4;
        trsplit_body(W2, w20, w21, C_, CP_, bx, by, r, tid);
    }
}

// ---------------------------------------------------------------------------
// HMMA fp16 GEMM with 3-product 2-limb split. (unchanged — proven)
// ---------------------------------------------------------------------------
#define TILE_B 8192
#define STAGE_B (4 * TILE_B)
#define NSTAGE 3
#define NCHUNK 16
#define EPI_PITCH_H 272
#define EPI_PITCH_F 528

template <bool SPLIT>
__global__ void __launch_bounds__(256, 2) tc_gemm(
    const __half* __restrict__ A0, const __half* __restrict__ A1, long long aStr,
    const __half* __restrict__ B0, const __half* __restrict__ B1, long long bStr,
    const float* __restrict__ bias, int biasStr, int Nreal,
    float* __restrict__ outF, int outLd,
    __half* __restrict__ O0, __half* __restrict__ O1)
{
    extern __shared__ __align__(16) char dsm[];
    const uint32_t sbase = smem_u32(dsm);

    const int tid = threadIdx.x;
    const int warp = tid >> 5, lane = tid & 31;
    const int bz = blockIdx.z;
    const int m0 = blockIdx.y * 128, n0 = blockIdx.x * 128;
    const int warpM = (warp >> 2) * 64;
    const int warpN = (warp & 3) * 32;

    const char* gp[4];
    gp[0] = (const char*)A0 + ((size_t)bz * aStr + (size_t)m0 * D_) * 2;
    gp[1] = (const char*)A1 + ((size_t)bz * aStr + (size_t)m0 * D_) * 2;
    gp[2] = (const char*)B0 + ((size_t)bz * bStr + (size_t)n0 * D_) * 2;
    gp[3] = (const char*)B1 + ((size_t)bz * bStr + (size_t)n0 * D_) * 2;

    const int ldRow0 = tid >> 2, ldC0 = tid & 3;
    const int ldRow1 = (tid + 256) >> 2, ldC1 = (tid + 256) & 3;
    const uint32_t ldDst0 = (uint32_t)ldRow0 * 64 + (uint32_t)((ldC0 ^ ((ldRow0 >> 1) & 3)) << 4);
    const uint32_t ldDst1 = (uint32_t)ldRow1 * 64 + (uint32_t)((ldC1 ^ ((ldRow1 >> 1) & 3)) << 4);
    const size_t ldSrc0 = (size_t)ldRow0 * 1024 + ldC0 * 16;
    const size_t ldSrc1 = (size_t)ldRow1 * 1024 + ldC1 * 16;

    auto load_stage = [&](int kk, int buf) {
        const size_t koff = (size_t)kk * 64;
#pragma unroll
        for (int t = 0; t < 4; t++) {
            uint32_t sb = sbase + buf * STAGE_B + t * TILE_B;
            const char* g = gp[t] + koff;
            cp_async16(sb + ldDst0, g + ldSrc0);
            cp_async16(sb + ldDst1, g + ldSrc1);
        }
        cp_commit();
    };

    float acc[4][4][4];
#pragma unroll
    for (int i = 0; i < 4; i++)
#pragma unroll
        for (int j = 0; j < 4; j++)
#pragma unroll
            for (int r = 0; r < 4; r++) acc[i][j][r] = 0.0f;

    load_stage(0, 0);
    load_stage(1, 1);

    const int rowA = warpM + (lane & 15);
    const uint32_t swA = (uint32_t)((rowA >> 1) & 3);
    const uint32_t cA = (uint32_t)(lane >> 4);
    const uint32_t aBase = (uint32_t)rowA * 64;

    const int rowB = warpN + (lane & 7) + ((lane >> 4) & 1) * 8;
    const uint32_t swB = (uint32_t)((rowB >> 1) & 3);
    const uint32_t cB = (uint32_t)((lane >> 3) & 1);
    const uint32_t bBase = (uint32_t)rowB * 64;

    for (int kk = 0; kk < NCHUNK; kk++) {
        if (kk == NCHUNK - 1) cp_wait<0>(); else cp_wait<1>();
        __syncthreads();
        if (kk + 2 < NCHUNK) load_stage(kk + 2, (kk + 2) % NSTAGE);

        const uint32_t sb = sbase + (kk % NSTAGE) * STAGE_B;

#pragma unroll
        for (int ks = 0; ks < 2; ks++) {
            const uint32_t aOff = aBase + (((ks * 2 + cA) ^ swA) << 4);
            const uint32_t bOff = bBase + (((ks * 2 + cB) ^ swB) << 4);
            uint32_t a0f[4][4], b0f[2][4];
#pragma unroll
            for (int i = 0; i < 4; i++)
                ldsm4(a0f[i], sb + 0 * TILE_B + aOff + i * 1024);
#pragma unroll
            for (int jp = 0; jp < 2; jp++)
                ldsm4(b0f[jp], sb + 2 * TILE_B + bOff + jp * 1024);
#pragma unroll
            for (int i = 0; i < 4; i++)
#pragma unroll
                for (int j = 0; j < 4; j++)
                    mma16816(acc[i][j], a0f[i], b0f[j >> 1][(j & 1) * 2],
                             b0f[j >> 1][(j & 1) * 2 + 1]);
            {
                uint32_t b1f[2][4];
#pragma unroll
                for (int jp = 0; jp < 2; jp++)
                    ldsm4(b1f[jp], sb + 3 * TILE_B + bOff + jp * 1024);
#pragma unroll
                for (int i = 0; i < 4; i++)
#pragma unroll
                    for (int j = 0; j < 4; j++)
                        mma16816(acc[i][j], a0f[i], b1f[j >> 1][(j & 1) * 2],
                                 b1f[j >> 1][(j & 1) * 2 + 1]);
            }
            {
                uint32_t a1f[4][4];
#pragma unroll
                for (int i = 0; i < 4; i++)
                    ldsm4(a1f[i], sb + 1 * TILE_B + aOff + i * 1024);
#pragma unroll
                for (int i = 0; i < 4; i++)
#pragma unroll
                    for (int j = 0; j < 4; j++)
                        mma16816(acc[i][j], a1f[i], b0f[j >> 1][(j & 1) * 2],
                                 b0f[j >> 1][(j & 1) * 2 + 1]);
            }
        }
    }

    // ---------------- epilogue: smem-staged, coalesced global writes --------
    __syncthreads();

    const int rBase = warpM + (lane >> 2);
    const int cBaseH = warpN + (lane & 3) * 2;

    float bj[4][2];
#pragma unroll
    for (int j = 0; j < 4; j++)
#pragma unroll
        for (int t = 0; t < 2; t++) {
            int n = n0 + cBaseH + j * 8 + t;
            bj[j][t] = (SPLIT || n < Nreal) ? bias[bz * biasStr + n] : 0.0f;
        }

    if (SPLIT) {
#pragma unroll
        for (int i = 0; i < 4; i++)
#pragma unroll
            for (int j = 0; j < 4; j++)
#pragma unroll
                for (int half = 0; half < 2; half++) {
                    const int r = rBase + i * 16 + half * 8;
                    const int c = cBaseH + j * 8;
                    float v0 = fmaxf(acc[i][j][half * 2]     + bj[j][0], 0.0f);
                    float v1 = fmaxf(acc[i][j][half * 2 + 1] + bj[j][1], 0.0f);
                    __half a0, b0, a1, b1;
                    split2(v0, a0, b0);
                    split2(v1, a1, b1);
                    *(__half2*)(dsm + r * EPI_PITCH_H + c * 2) = __half2(a0, a1);
                    *(__half2*)(dsm + 128 * EPI_PITCH_H + r * EPI_PITCH_H + c * 2) = __half2(b0, b1);
                }
        __syncthreads();
#pragma unroll
        for (int it = 0; it < 8; it++) {
            int idx = tid + it * 256;
            int r = idx >> 4, c16 = idx & 15;
            float4 w0 = *(const float4*)(dsm + r * EPI_PITCH_H + c16 * 16);
            float4 w1 = *(const float4*)(dsm + 128 * EPI_PITCH_H + r * EPI_PITCH_H + c16 * 16);
            size_t gb = ((size_t)bz * B_ + m0 + r) * D_ + n0 + c16 * 8;
            *(float4*)&O0[gb] = w0;
            *(float4*)&O1[gb] = w1;
        }
    } else {
#pragma unroll
        for (int i = 0; i < 4; i++)
#pragma unroll
            for (int j = 0; j < 4; j++)
#pragma unroll
                for (int half = 0; half < 2; half++) {
                    const int r = rBase + i * 16 + half * 8;
                    const int c = cBaseH + j * 8;
                    float2 vv = make_float2(acc[i][j][half * 2]     + bj[j][0],
                                            acc[i][j][half * 2 + 1] + bj[j][1]);
                    *(float2*)(dsm + r * EPI_PITCH_F + c * 4) = vv;
                }
        __syncthreads();
#pragma unroll
        for (int it = 0; it < 16; it++) {
            int idx = tid + it * 256;
            int r = idx >> 5, c4 = idx & 31;
            float4 w = *(const float4*)(dsm + r * EPI_PITCH_F + c4 * 16);
            *(float4*)&outF[((size_t)(m0 + r) * K_ + bz) * outLd + n0 + c4 * 4] = w;
        }
    }
}

// ---------------------------------------------------------------------------
// Gating kernel v6 — logits live in registers through max+exp phases;
// slg written once (combine-only read). Z/G finalize + selection in warp 0.
// ---------------------------------------------------------------------------
__global__ void __launch_bounds__(256, 4) gating_kernel(
    const int* __restrict__ n_exp,
    float* __restrict__ out_logits,
    float* __restrict__ out_gates)
{
    __shared__ float4 slg[K_][256];    // 32 KB: [expert][thread] (combine only)
    __shared__ float sred[8][8];       // [warp][expert]
    __shared__ float sredG[8][36];     // [warp][pair]
    __shared__ float smax[K_], sZ[K_], sG[K_ * K_], sgate[K_];

    const int b = blockIdx.x, tid = threadIdx.x;
    const int w = tid >> 5, lane = tid & 31;
    const bool act = (tid < 250);
    const int c = tid * 4;

    const float* lrow = g_logits + (size_t)b * K_ * CP_;

    // phase 1: batched loads -> regs; stash to smem; per-expert max partials
    float4 v[K_];
#pragma unroll
    for (int k = 0; k < K_; k++)
        v[k] = act ? *(const float4*)(lrow + (size_t)k * CP_ + c)
                   : make_float4(-INFINITY, -INFINITY, -INFINITY, -INFINITY);
#pragma unroll
    for (int k = 0; k < K_; k++) slg[k][tid] = v[k];
#pragma unroll
    for (int k = 0; k < K_; k++) {
        float m = fmaxf(fmaxf(v[k].x, v[k].y), fmaxf(v[k].z, v[k].w));
#pragma unroll
        for (int o = 16; o > 0; o >>= 1) m = fmaxf(m, __shfl_xor_sync(0xffffffffu, m, o));
        if (lane == 0) sred[w][k] = m;
    }
    __syncthreads();
    if (tid < K_) {
        float m = sred[0][tid];
#pragma unroll
        for (int j = 1; j < 8; j++) m = fmaxf(m, sred[j][tid]);
        smax[tid] = m;
    }
    __syncthreads();

    // phase 2: exp from registers; sum + gram partials
    float se[K_][4];
#pragma unroll
    for (int k = 0; k < K_; k++) {
        float m = smax[k];
        se[k][0] = __expf(v[k].x - m);
        se[k][1] = __expf(v[k].y - m);
        se[k][2] = __expf(v[k].z - m);
        se[k][3] = __expf(v[k].w - m);
        float z = se[k][0] + se[k][1] + se[k][2] + se[k][3];
#pragma unroll
        for (int o = 16; o > 0; o >>= 1) z += __shfl_xor_sync(0xffffffffu, z, o);
        if (lane == 0) sred[w][k] = z;
    }
    {
        int p = 0;
#pragma unroll
        for (int i = 0; i < K_; i++)
#pragma unroll
            for (int j = i; j < K_; j++) {
                float s = se[i][0] * se[j][0] + se[i][1] * se[j][1] +
                          se[i][2] * se[j][2] + se[i][3] * se[j][3];
#pragma unroll
                for (int o = 16; o > 0; o >>= 1) s += __shfl_xor_sync(0xffffffffu, s, o);
                if (lane == 0) sredG[w][p] = s;
                p++;
            }
    }
    __syncthreads();

    // finalize Z + Gram in warp 0, then selection under __syncwarp
    if (w == 0) {
        if (lane < K_) {
            float z = 0.0f;
#pragma unroll
            for (int j = 0; j < 8; j++) z += sred[j][lane];
            sZ[lane] = z;
        }
#pragma unroll
        for (int pp = 0; pp < 2; pp++) {
            int p = lane + pp * 32;
            if (p < 36) {
                float s = 0.0f;
#pragma unroll
                for (int j = 0; j < 8; j++) s += sredG[j][p];
                int i = 0, q = p;
                while (q >= K_ - i) { q -= (K_ - i); i++; }
                int jj = i + q;
                float g = s / (sZ[i] * sZ[jj]);   // sZ[i] valid: lane<K_ wrote before? need sync
                sG[i * K_ + jj] = g;
                sG[jj * K_ + i] = g;
            }
        }
    }
    __syncthreads();   // publish sZ/sG written by warp 0 (also orders the sZ read above)

    // NOTE: the Gram finalize above reads sZ written by lanes of the same warp.
    // Warp-synchronous execution guarantees lane 0..7's sZ stores complete
    // before lane p's read only within the same instruction stream; to be
    // safe the division is re-done here from raw sums is avoided by the
    // barrier above — but the read happened BEFORE the barrier. Fix: compute
    // g from sred directly (no sZ dependency) was not done, so instead the
    // selection below recomputes normalization safely from sZ.

    if (tid < 8) {
        const unsigned MSK = 0xFFu;
        const int i = tid;
        float nrmv = sqrtf(sG[i * K_ + i]) + EPSV;
        float confv = 1.0f / sZ[i];
        float Srow[K_];
#pragma unroll
        for (int j = 0; j < K_; j++) {
            float nrmj = __shfl_sync(MSK, nrmv, j, 8);
            Srow[j] = sG[i * K_ + j] / (nrmv * nrmj);
        }

        float bv = confv; int bi = i;
#pragma unroll
        for (int o = 4; o > 0; o >>= 1) {
            float ov = __shfl_down_sync(MSK, bv, o, 8);
            int oi = __shfl_down_sync(MSK, bi, o, 8);
            if (ov > bv || (ov == bv && oi < bi)) { bv = ov; bi = oi; }
        }
        bi = __shfl_sync(MSK, bi, 0, 8);
        unsigned selMask = 1u << bi;

        int n = n_exp[b];
        for (int t = 1; t < K_; t++) {
            float dist;
            if (selMask & (1u << i)) dist = -INFINITY;
            else {
                float ms = -INFINITY;
#pragma unroll
                for (int j = 0; j < K_; j++)
                    if (selMask & (1u << j)) ms = fmaxf(ms, Srow[j]);
                dist = 1.0f - ms;
            }
            float av = dist; int ai = i;
#pragma unroll
            for (int o = 4; o > 0; o >>= 1) {
                float ov = __shfl_down_sync(MSK, av, o, 8);
                int oi = __shfl_down_sync(MSK, ai, o, 8);
                if (ov > av || (ov == av && oi < ai)) { av = ov; ai = oi; }
            }
            ai = __shfl_sync(MSK, ai, 0, 8);
            if (t < n) selMask |= 1u << ai;
        }

        float gl = ((selMask >> i) & 1u) ? confv / TEMPV : NEGV / TEMPV;
        float gm = gl;
#pragma unroll
        for (int o = 4; o > 0; o >>= 1) gm = fmaxf(gm, __shfl_xor_sync(MSK, gm, o, 8));
        float ge = __expf(gl - gm);
        float gs = ge;
#pragma unroll
        for (int o = 4; o > 0; o >>= 1) gs += __shfl_xor_sync(MSK, gs, o, 8);
        sgate[i] = ge / gs;
    }
    __syncthreads();

    // combine: read slg (single smem read of the logits)
    if (act) {
        float4 a4 = make_float4(0.f, 0.f, 0.f, 0.f);
#pragma unroll
        for (int k = 0; k < K_; k++) {
            float g = sgate[k];
            float4 vv = slg[k][tid];
            a4.x += g * vv.x; a4.y += g * vv.y;
            a4.z += g * vv.z; a4.w += g * vv.w;
        }
        *(float4*)(out_logits + (size_t)b * C_ + c) = a4;
    }
    if (tid < K_) out_gates[(size_t)b * K_ + tid] = sgate[tid];
}

// ---------------------------------------------------------------------------
extern "C" void kernel_launch(void* const* d_in, const int* in_sizes, int n_in,
                              void* d_out, int out_size)
{
    const float* z    = (const float*)d_in[0];
    const int*   nexp = (const int*)d_in[1];
    const float* W1   = (const float*)d_in[2];
    const float* b1   = (const float*)d_in[3];
    const float* W2   = (const float*)d_in[4];
    const float* b2   = (const float*)d_in[5];
    float* out = (float*)d_out;

    __half *z0, *z1, *w10, *w11, *w20, *w21, *h0, *h1;
    float* lg;
    cudaGetSymbolAddress((void**)&z0, g_z0);   cudaGetSymbolAddress((void**)&z1, g_z1);
    cudaGetSymbolAddress((void**)&w10, g_w1t0); cudaGetSymbolAddress((void**)&w11, g_w1t1);
    cudaGetSymbolAddress((void**)&w20, g_w2t0); cudaGetSymbolAddress((void**)&w21, g_w2t1);
    cudaGetSymbolAddress((void**)&h0, g_h0);   cudaGetSymbolAddress((void**)&h1, g_h1);
    cudaGetSymbolAddress((void**)&lg, g_logits);

    cudaFuncSetAttribute(tc_gemm<true>,  cudaFuncAttributeMaxDynamicSharedMemorySize, NSTAGE * STAGE_B);
    cudaFuncSetAttribute(tc_gemm<false>, cudaFuncAttributeMaxDynamicSharedMemorySize, NSTAGE * STAGE_B);

    // merged input conversions (z, W1, W2 in one launch)
    convert_all_kernel<<<NB_Z + NB_W1 + NB_W2, 256>>>(
        z, W1, W2, z0, z1, w10, w11, w20, w21);

    // GEMM1: h = relu(z @ W1 + b1), re-split into 2 fp16 limbs
    tc_gemm<true><<<dim3(D_ / 128, B_ / 128, K_), 256, NSTAGE * STAGE_B>>>(
        z0, z1, 0LL,
        w10, w11, (long long)D_ * D_,
        b1, D_, D_, nullptr, 0, h0, h1);

    // GEMM2: logits = h @ W2 + b2 (fp32, padded to CP_)
    tc_gemm<false><<<dim3(CP_ / 128, B_ / 128, K_), 256, NSTAGE * STAGE_B>>>(
        h0, h1, (long long)B_ * D_,
        w20, w21, (long long)CP_ * D_,
        b2, C_, C_, lg, CP_, nullptr, nullptr);

    // gating + combine
    gating_kernel<<<B_, 256>>>(nexp, out, out + (size_t)B_ * C_);
}

// round 16
// speedup vs baseline: 1.0410x; 1.0113x over previous
#include <cuda_runtime.h>
#include <cuda_fp16.h>
#include <cstdint>
#include <math.h>

#define B_ 8192
#define D_ 512
#define C_ 1000
#define CP_ 1024
#define K_ 8
#define EPSV 1e-8f
#define TEMPV 0.2f
#define NEGV -10000.0f

// ---------------------------------------------------------------------------
// Scratch (__device__ globals)
// ---------------------------------------------------------------------------
__device__ __half g_z0[(size_t)B_ * D_];
__device__ __half g_z1[(size_t)B_ * D_];
__device__ __half g_w1t0[(size_t)K_ * D_ * D_];
__device__ __half g_w1t1[(size_t)K_ * D_ * D_];
__device__ __half g_w2t0[(size_t)K_ * CP_ * D_];
__device__ __half g_w2t1[(size_t)K_ * CP_ * D_];
__device__ __half g_h0[(size_t)K_ * B_ * D_];
__device__ __half g_h1[(size_t)K_ * B_ * D_];
__device__ float g_logits[(size_t)B_ * K_ * CP_];

// ---------------------------------------------------------------------------
// PTX helpers
// ---------------------------------------------------------------------------
__device__ __forceinline__ uint32_t smem_u32(const void* p) {
    uint32_t a;
    asm("{ .reg .u64 t; cvta.to.shared.u64 t, %1; cvt.u32.u64 %0, t; }" : "=r"(a) : "l"(p));
    return a;
}
__device__ __forceinline__ void cp_async16(uint32_t s, const void* g) {
    asm volatile("cp.async.cg.shared.global [%0], [%1], 16;" :: "r"(s), "l"(g));
}
__device__ __forceinline__ void cp_commit() { asm volatile("cp.async.commit_group;"); }
template <int N>
__device__ __forceinline__ void cp_wait() { asm volatile("cp.async.wait_group %0;" :: "n"(N)); }

__device__ __forceinline__ void ldsm4(uint32_t* r, uint32_t addr) {
    asm volatile("ldmatrix.sync.aligned.m8n8.x4.shared.b16 {%0,%1,%2,%3}, [%4];"
                 : "=r"(r[0]), "=r"(r[1]), "=r"(r[2]), "=r"(r[3]) : "r"(addr));
}
__device__ __forceinline__ void mma16816(float* c, const uint32_t* a, uint32_t b0, uint32_t b1) {
    asm volatile(
        "mma.sync.aligned.m16n8k16.row.col.f32.f16.f16.f32 "
        "{%0,%1,%2,%3}, {%4,%5,%6,%7}, {%8,%9}, {%0,%1,%2,%3};"
        : "+f"(c[0]), "+f"(c[1]), "+f"(c[2]), "+f"(c[3])
        : "r"(a[0]), "r"(a[1]), "r"(a[2]), "r"(a[3]), "r"(b0), "r"(b1));
}

// 2-limb fp16 split: x = a + b + O(2^-22 |x|)
__device__ __forceinline__ void split2(float x, __half& a, __half& b) {
    a = __float2half_rn(x);
    b = __float2half_rn(x - __half2float(a));
}

// ---------------------------------------------------------------------------
// Merged conversion kernel (one launch: z split + W1/W2 transpose-split)
// ---------------------------------------------------------------------------
#define NB_Z  (B_ * D_ / 4 / 256)            // 4096
#define NB_W1 ((D_ / 32) * (D_ / 32) * K_)   // 2048
#define NB_W2 ((CP_ / 32) * (D_ / 32) * K_)  // 4096

__device__ __forceinline__ void trsplit_body(
    const float* __restrict__ in, __half* __restrict__ o0, __half* __restrict__ o1,
    int Nin, int Npad, int bx, int by, int k, int tid)
{
    __shared__ float t[32][33];
    const int n0 = bx * 32, d0 = by * 32;
    const int tx = tid & 31, ty = tid >> 5;
    const float* src = in + (size_t)k * D_ * Nin;
#pragma unroll
    for (int r = 0; r < 4; r++) {
        int d = d0 + ty + r * 8, n = n0 + tx;
        t[ty + r * 8][tx] = (n < Nin) ? src[(size_t)d * Nin + n] : 0.0f;
    }
    __syncthreads();
    size_t obase = (size_t)k * Npad * D_;
#pragma unroll
    for (int r = 0; r < 4; r++) {
        int nl = ty + r * 8;
        float v = t[tx][nl];
        __half a, b;
        split2(v, a, b);
        size_t oi = obase + (size_t)(n0 + nl) * D_ + d0 + tx;
        o0[oi] = a; o1[oi] = b;
    }
}

__global__ void __launch_bounds__(256) convert_all_kernel(
    const float* __restrict__ z, const float* __restrict__ W1,
    const float* __restrict__ W2,
    __half* __restrict__ z0, __half* __restrict__ z1,
    __half* __restrict__ w10, __half* __restrict__ w11,
    __half* __restrict__ w20, __half* __restrict__ w21)
{
    const int blk = blockIdx.x;
    const int tid = threadIdx.x;
    if (blk < NB_Z) {
        int i = blk * 256 + tid;
        float4 v = ((const float4*)z)[i];
        __half a0, b0, a1, b1, a2, b2, a3, b3;
        split2(v.x, a0, b0); split2(v.y, a1, b1);
        split2(v.z, a2, b2); split2(v.w, a3, b3);
        ((__half2*)z0)[i * 2]     = __half2(a0, a1);
        ((__half2*)z0)[i * 2 + 1] = __half2(a2, a3);
        ((__half2*)z1)[i * 2]     = __half2(b0, b1);
        ((__half2*)z1)[i * 2 + 1] = __half2(b2, b3);
    } else if (blk < NB_Z + NB_W1) {
        int r = blk - NB_Z;
        int bx = r & 15; r >>= 4;
        int by = r & 15; r >>= 4;
        trsplit_body(W1, w10, w11, D_, D_, bx, by, r, tid);
    } else {
        int r = blk - NB_Z - NB_W1;
        int bx = r & 31; r >>= 5;
        int by = r & 15; r >>= 4;
        trsplit_body(W2, w20, w21, C_, CP_, bx, by, r, tid);
    }
}

// ---------------------------------------------------------------------------
// HMMA fp16 GEMM with 3-product 2-limb split. (unchanged — proven)
// ---------------------------------------------------------------------------
#define TILE_B 8192
#define STAGE_B (4 * TILE_B)
#define NSTAGE 3
#define NCHUNK 16
#define EPI_PITCH_H 272
#define EPI_PITCH_F 528

template <bool SPLIT>
__global__ void __launch_bounds__(256, 2) tc_gemm(
    const __half* __restrict__ A0, const __half* __restrict__ A1, long long aStr,
    const __half* __restrict__ B0, const __half* __restrict__ B1, long long bStr,
    const float* __restrict__ bias, int biasStr, int Nreal,
    float* __restrict__ outF, int outLd,
    __half* __restrict__ O0, __half* __restrict__ O1)
{
    extern __shared__ __align__(16) char dsm[];
    const uint32_t sbase = smem_u32(dsm);

    const int tid = threadIdx.x;
    const int warp = tid >> 5, lane = tid & 31;
    const int bz = blockIdx.z;
    const int m0 = blockIdx.y * 128, n0 = blockIdx.x * 128;
    const int warpM = (warp >> 2) * 64;
    const int warpN = (warp & 3) * 32;

    const char* gp[4];
    gp[0] = (const char*)A0 + ((size_t)bz * aStr + (size_t)m0 * D_) * 2;
    gp[1] = (const char*)A1 + ((size_t)bz * aStr + (size_t)m0 * D_) * 2;
    gp[2] = (const char*)B0 + ((size_t)bz * bStr + (size_t)n0 * D_) * 2;
    gp[3] = (const char*)B1 + ((size_t)bz * bStr + (size_t)n0 * D_) * 2;

    const int ldRow0 = tid >> 2, ldC0 = tid & 3;
    const int ldRow1 = (tid + 256) >> 2, ldC1 = (tid + 256) & 3;
    const uint32_t ldDst0 = (uint32_t)ldRow0 * 64 + (uint32_t)((ldC0 ^ ((ldRow0 >> 1) & 3)) << 4);
    const uint32_t ldDst1 = (uint32_t)ldRow1 * 64 + (uint32_t)((ldC1 ^ ((ldRow1 >> 1) & 3)) << 4);
    const size_t ldSrc0 = (size_t)ldRow0 * 1024 + ldC0 * 16;
    const size_t ldSrc1 = (size_t)ldRow1 * 1024 + ldC1 * 16;

    auto load_stage = [&](int kk, int buf) {
        const size_t koff = (size_t)kk * 64;
#pragma unroll
        for (int t = 0; t < 4; t++) {
            uint32_t sb = sbase + buf * STAGE_B + t * TILE_B;
            const char* g = gp[t] + koff;
            cp_async16(sb + ldDst0, g + ldSrc0);
            cp_async16(sb + ldDst1, g + ldSrc1);
        }
        cp_commit();
    };

    float acc[4][4][4];
#pragma unroll
    for (int i = 0; i < 4; i++)
#pragma unroll
        for (int j = 0; j < 4; j++)
#pragma unroll
            for (int r = 0; r < 4; r++) acc[i][j][r] = 0.0f;

    load_stage(0, 0);
    load_stage(1, 1);

    const int rowA = warpM + (lane & 15);
    const uint32_t swA = (uint32_t)((rowA >> 1) & 3);
    const uint32_t cA = (uint32_t)(lane >> 4);
    const uint32_t aBase = (uint32_t)rowA * 64;

    const int rowB = warpN + (lane & 7) + ((lane >> 4) & 1) * 8;
    const uint32_t swB = (uint32_t)((rowB >> 1) & 3);
    const uint32_t cB = (uint32_t)((lane >> 3) & 1);
    const uint32_t bBase = (uint32_t)rowB * 64;

    for (int kk = 0; kk < NCHUNK; kk++) {
        if (kk == NCHUNK - 1) cp_wait<0>(); else cp_wait<1>();
        __syncthreads();
        if (kk + 2 < NCHUNK) load_stage(kk + 2, (kk + 2) % NSTAGE);

        const uint32_t sb = sbase + (kk % NSTAGE) * STAGE_B;

#pragma unroll
        for (int ks = 0; ks < 2; ks++) {
            const uint32_t aOff = aBase + (((ks * 2 + cA) ^ swA) << 4);
            const uint32_t bOff = bBase + (((ks * 2 + cB) ^ swB) << 4);
            uint32_t a0f[4][4], b0f[2][4];
#pragma unroll
            for (int i = 0; i < 4; i++)
                ldsm4(a0f[i], sb + 0 * TILE_B + aOff + i * 1024);
#pragma unroll
            for (int jp = 0; jp < 2; jp++)
                ldsm4(b0f[jp], sb + 2 * TILE_B + bOff + jp * 1024);
#pragma unroll
            for (int i = 0; i < 4; i++)
#pragma unroll
                for (int j = 0; j < 4; j++)
                    mma16816(acc[i][j], a0f[i], b0f[j >> 1][(j & 1) * 2],
                             b0f[j >> 1][(j & 1) * 2 + 1]);
            {
                uint32_t b1f[2][4];
#pragma unroll
                for (int jp = 0; jp < 2; jp++)
                    ldsm4(b1f[jp], sb + 3 * TILE_B + bOff + jp * 1024);
#pragma unroll
                for (int i = 0; i < 4; i++)
#pragma unroll
                    for (int j = 0; j < 4; j++)
                        mma16816(acc[i][j], a0f[i], b1f[j >> 1][(j & 1) * 2],
                                 b1f[j >> 1][(j & 1) * 2 + 1]);
            }
            {
                uint32_t a1f[4][4];
#pragma unroll
                for (int i = 0; i < 4; i++)
                    ldsm4(a1f[i], sb + 1 * TILE_B + aOff + i * 1024);
#pragma unroll
                for (int i = 0; i < 4; i++)
#pragma unroll
                    for (int j = 0; j < 4; j++)
                        mma16816(acc[i][j], a1f[i], b0f[j >> 1][(j & 1) * 2],
                                 b0f[j >> 1][(j & 1) * 2 + 1]);
            }
        }
    }

    // ---------------- epilogue: smem-staged, coalesced global writes --------
    __syncthreads();

    const int rBase = warpM + (lane >> 2);
    const int cBaseH = warpN + (lane & 3) * 2;

    float bj[4][2];
#pragma unroll
    for (int j = 0; j < 4; j++)
#pragma unroll
        for (int t = 0; t < 2; t++) {
            int n = n0 + cBaseH + j * 8 + t;
            bj[j][t] = (SPLIT || n < Nreal) ? bias[bz * biasStr + n] : 0.0f;
        }

    if (SPLIT) {
#pragma unroll
        for (int i = 0; i < 4; i++)
#pragma unroll
            for (int j = 0; j < 4; j++)
#pragma unroll
                for (int half = 0; half < 2; half++) {
                    const int r = rBase + i * 16 + half * 8;
                    const int c = cBaseH + j * 8;
                    float v0 = fmaxf(acc[i][j][half * 2]     + bj[j][0], 0.0f);
                    float v1 = fmaxf(acc[i][j][half * 2 + 1] + bj[j][1], 0.0f);
                    __half a0, b0, a1, b1;
                    split2(v0, a0, b0);
                    split2(v1, a1, b1);
                    *(__half2*)(dsm + r * EPI_PITCH_H + c * 2) = __half2(a0, a1);
                    *(__half2*)(dsm + 128 * EPI_PITCH_H + r * EPI_PITCH_H + c * 2) = __half2(b0, b1);
                }
        __syncthreads();
#pragma unroll
        for (int it = 0; it < 8; it++) {
            int idx = tid + it * 256;
            int r = idx >> 4, c16 = idx & 15;
            float4 w0 = *(const float4*)(dsm + r * EPI_PITCH_H + c16 * 16);
            float4 w1 = *(const float4*)(dsm + 128 * EPI_PITCH_H + r * EPI_PITCH_H + c16 * 16);
            size_t gb = ((size_t)bz * B_ + m0 + r) * D_ + n0 + c16 * 8;
            *(float4*)&O0[gb] = w0;
            *(float4*)&O1[gb] = w1;
        }
    } else {
#pragma unroll
        for (int i = 0; i < 4; i++)
#pragma unroll
            for (int j = 0; j < 4; j++)
#pragma unroll
                for (int half = 0; half < 2; half++) {
                    const int r = rBase + i * 16 + half * 8;
                    const int c = cBaseH + j * 8;
                    float2 vv = make_float2(acc[i][j][half * 2]     + bj[j][0],
                                            acc[i][j][half * 2 + 1] + bj[j][1]);
                    *(float2*)(dsm + r * EPI_PITCH_F + c * 4) = vv;
                }
        __syncthreads();
#pragma unroll
        for (int it = 0; it < 16; it++) {
            int idx = tid + it * 256;
            int r = idx >> 5, c4 = idx & 31;
            float4 w = *(const float4*)(dsm + r * EPI_PITCH_F + c4 * 16);
            *(float4*)&outF[((size_t)(m0 + r) * K_ + bz) * outLd + n0 + c4 * 4] = w;
        }
    }
}

// ---------------------------------------------------------------------------
// Gating kernel v7 — v6 register-resident base + 3-step Gram reduction
// (butterfly within 8-lane groups, 32-partial finalize; sG holds RAW sums,
// normalization folded into the selection like R13).
// ---------------------------------------------------------------------------
__global__ void __launch_bounds__(256, 4) gating_kernel(
    const int* __restrict__ n_exp,
    float* __restrict__ out_logits,
    float* __restrict__ out_gates)
{
    __shared__ float4 slg[K_][256];    // 32 KB: [expert][thread] (combine only)
    __shared__ float sred[8][8];       // [warp][expert]
    __shared__ float sredG[32][36];    // [warp*4+group][pair]
    __shared__ float smax[K_], sZ[K_], sG[K_ * K_], sgate[K_];

    const int b = blockIdx.x, tid = threadIdx.x;
    const int w = tid >> 5, lane = tid & 31;
    const bool act = (tid < 250);
    const int c = tid * 4;
    const int grp = lane >> 3;         // 0..3

    const float* lrow = g_logits + (size_t)b * K_ * CP_;

    // phase 1: batched loads -> regs; stash to smem; per-expert max partials
    float4 v[K_];
#pragma unroll
    for (int k = 0; k < K_; k++)
        v[k] = act ? *(const float4*)(lrow + (size_t)k * CP_ + c)
                   : make_float4(-INFINITY, -INFINITY, -INFINITY, -INFINITY);
#pragma unroll
    for (int k = 0; k < K_; k++) slg[k][tid] = v[k];
#pragma unroll
    for (int k = 0; k < K_; k++) {
        float m = fmaxf(fmaxf(v[k].x, v[k].y), fmaxf(v[k].z, v[k].w));
#pragma unroll
        for (int o = 16; o > 0; o >>= 1) m = fmaxf(m, __shfl_xor_sync(0xffffffffu, m, o));
        if (lane == 0) sred[w][k] = m;
    }
    __syncthreads();
    if (tid < K_) {
        float m = sred[0][tid];
#pragma unroll
        for (int j = 1; j < 8; j++) m = fmaxf(m, sred[j][tid]);
        smax[tid] = m;
    }
    __syncthreads();

    // phase 2: exp from registers; Z partials (5-step); Gram partials (3-step)
    float se[K_][4];
#pragma unroll
    for (int k = 0; k < K_; k++) {
        float m = smax[k];
        se[k][0] = __expf(v[k].x - m);
        se[k][1] = __expf(v[k].y - m);
        se[k][2] = __expf(v[k].z - m);
        se[k][3] = __expf(v[k].w - m);
        float z = se[k][0] + se[k][1] + se[k][2] + se[k][3];
#pragma unroll
        for (int o = 16; o > 0; o >>= 1) z += __shfl_xor_sync(0xffffffffu, z, o);
        if (lane == 0) sred[w][k] = z;
    }
    {
        int p = 0;
#pragma unroll
        for (int i = 0; i < K_; i++)
#pragma unroll
            for (int j = i; j < K_; j++) {
                float s = se[i][0] * se[j][0] + se[i][1] * se[j][1] +
                          se[i][2] * se[j][2] + se[i][3] * se[j][3];
                s += __shfl_xor_sync(0xffffffffu, s, 1);
                s += __shfl_xor_sync(0xffffffffu, s, 2);
                s += __shfl_xor_sync(0xffffffffu, s, 4);
                if ((lane & 7) == 0) sredG[w * 4 + grp][p] = s;
                p++;
            }
    }
    __syncthreads();

    // finalize: Z (tid<8) and raw Gram (tid 32..67) in parallel
    if (tid < K_) {
        float z = 0.0f;
#pragma unroll
        for (int j = 0; j < 8; j++) z += sred[j][tid];
        sZ[tid] = z;
    }
    if (tid >= 32 && tid < 68) {
        int p = tid - 32;
        float ssum = 0.0f;
#pragma unroll
        for (int j = 0; j < 32; j++) ssum += sredG[j][p];
        int i = 0, q = p;
        while (q >= K_ - i) { q -= (K_ - i); i++; }
        int jj = i + q;
        sG[i * K_ + jj] = ssum;   // RAW sum (normalized in selection)
        sG[jj * K_ + i] = ssum;
    }
    __syncthreads();

    // greedy selection — lanes 0..7 of warp 0 (normalizes raw sums)
    if (tid < 8) {
        const unsigned MSK = 0xFFu;
        const int i = tid;
        float zz = sZ[i];
        float gii = sG[i * K_ + i] / (zz * zz);
        float nrmv = sqrtf(gii) + EPSV;
        float confv = 1.0f / zz;
        float Srow[K_];
#pragma unroll
        for (int j = 0; j < K_; j++) {
            float nrmj = __shfl_sync(MSK, nrmv, j, 8);
            float zj = __shfl_sync(MSK, zz, j, 8);
            Srow[j] = (sG[i * K_ + j] / (zz * zj)) / (nrmv * nrmj);
        }

        float bv = confv; int bi = i;
#pragma unroll
        for (int o = 4; o > 0; o >>= 1) {
            float ov = __shfl_down_sync(MSK, bv, o, 8);
            int oi = __shfl_down_sync(MSK, bi, o, 8);
            if (ov > bv || (ov == bv && oi < bi)) { bv = ov; bi = oi; }
        }
        bi = __shfl_sync(MSK, bi, 0, 8);
        unsigned selMask = 1u << bi;

        int n = n_exp[b];
        for (int t = 1; t < K_; t++) {
            float dist;
            if (selMask & (1u << i)) dist = -INFINITY;
            else {
                float ms = -INFINITY;
#pragma unroll
                for (int j = 0; j < K_; j++)
                    if (selMask & (1u << j)) ms = fmaxf(ms, Srow[j]);
                dist = 1.0f - ms;
            }
            float av = dist; int ai = i;
#pragma unroll
            for (int o = 4; o > 0; o >>= 1) {
                float ov = __shfl_down_sync(MSK, av, o, 8);
                int oi = __shfl_down_sync(MSK, ai, o, 8);
                if (ov > av || (ov == av && oi < ai)) { av = ov; ai = oi; }
            }
            ai = __shfl_sync(MSK, ai, 0, 8);
            if (t < n) selMask |= 1u << ai;
        }

        float gl = ((selMask >> i) & 1u) ? confv / TEMPV : NEGV / TEMPV;
        float gm = gl;
#pragma unroll
        for (int o = 4; o > 0; o >>= 1) gm = fmaxf(gm, __shfl_xor_sync(MSK, gm, o, 8));
        float ge = __expf(gl - gm);
        float gs = ge;
#pragma unroll
        for (int o = 4; o > 0; o >>= 1) gs += __shfl_xor_sync(MSK, gs, o, 8);
        sgate[i] = ge / gs;
    }
    __syncthreads();

    // combine: read slg once
    if (act) {
        float4 a4 = make_float4(0.f, 0.f, 0.f, 0.f);
#pragma unroll
        for (int k = 0; k < K_; k++) {
            float g = sgate[k];
            float4 vv = slg[k][tid];
            a4.x += g * vv.x; a4.y += g * vv.y;
            a4.z += g * vv.z; a4.w += g * vv.w;
        }
        *(float4*)(out_logits + (size_t)b * C_ + c) = a4;
    }
    if (tid < K_) out_gates[(size_t)b * K_ + tid] = sgate[tid];
}

// ---------------------------------------------------------------------------
extern "C" void kernel_launch(void* const* d_in, const int* in_sizes, int n_in,
                              void* d_out, int out_size)
{
    const float* z    = (const float*)d_in[0];
    const int*   nexp = (const int*)d_in[1];
    const float* W1   = (const float*)d_in[2];
    const float* b1   = (const float*)d_in[3];
    const float* W2   = (const float*)d_in[4];
    const float* b2   = (const float*)d_in[5];
    float* out = (float*)d_out;

    __half *z0, *z1, *w10, *w11, *w20, *w21, *h0, *h1;
    float* lg;
    cudaGetSymbolAddress((void**)&z0, g_z0);   cudaGetSymbolAddress((void**)&z1, g_z1);
    cudaGetSymbolAddress((void**)&w10, g_w1t0); cudaGetSymbolAddress((void**)&w11, g_w1t1);
    cudaGetSymbolAddress((void**)&w20, g_w2t0); cudaGetSymbolAddress((void**)&w21, g_w2t1);
    cudaGetSymbolAddress((void**)&h0, g_h0);   cudaGetSymbolAddress((void**)&h1, g_h1);
    cudaGetSymbolAddress((void**)&lg, g_logits);

    cudaFuncSetAttribute(tc_gemm<true>,  cudaFuncAttributeMaxDynamicSharedMemorySize, NSTAGE * STAGE_B);
    cudaFuncSetAttribute(tc_gemm<false>, cudaFuncAttributeMaxDynamicSharedMemorySize, NSTAGE * STAGE_B);

    // merged input conversions (z, W1, W2 in one launch)
    convert_all_kernel<<<NB_Z + NB_W1 + NB_W2, 256>>>(
        z, W1, W2, z0, z1, w10, w11, w20, w21);

    // GEMM1: h = relu(z @ W1 + b1), re-split into 2 fp16 limbs
    tc_gemm<true><<<dim3(D_ / 128, B_ / 128, K_), 256, NSTAGE * STAGE_B>>>(
        z0, z1, 0LL,
        w10, w11, (long long)D_ * D_,
        b1, D_, D_, nullptr, 0, h0, h1);

    // GEMM2: logits = h @ W2 + b2 (fp32, padded to CP_)
    tc_gemm<false><<<dim3(CP_ / 128, B_ / 128, K_), 256, NSTAGE * STAGE_B>>>(
        h0, h1, (long long)B_ * D_,
        w20, w21, (long long)CP_ * D_,
        b2, C_, C_, lg, CP_, nullptr, nullptr);

    // gating + combine
    gating_kernel<<<B_, 256>>>(nexp, out, out + (size_t)B_ * C_);
}